// round 8
// baseline (speedup 1.0000x reference)
#include <cuda_runtime.h>

#define BATCH 8
#define CH    512
#define HW    9216        // 96*96
#define NB    148         // one block per SM (all-resident for grid barrier)
#define NT    256         // full-path block size

#define CPY_NT   512      // copy block size
#define CPY_UNR  4        // float4 per thread

// Scratch for the gamma != 0 path (never exercised by this bench's data,
// but kept correct for arbitrary gamma).
__device__ float g_att[(size_t)BATCH * CH * CH];   // 8 MB

// Generation-based software grid barrier (gamma != 0 path only).
__device__ unsigned g_count = 0;
__device__ volatile unsigned g_gen = 0;

__device__ __forceinline__ void grid_barrier() {
    __syncthreads();
    __threadfence();
    if (threadIdx.x == 0) {
        unsigned gen = g_gen;
        if (atomicAdd(&g_count, 1) == NB - 1) {
            g_count = 0;
            __threadfence();
            g_gen = gen + 1;
        } else {
            while (g_gen == gen) { __nanosleep(64); }
        }
    }
    __syncthreads();
}

// ---------------------------------------------------------------------------
// Streaming copy: out = x, only when gamma == 0 (the full path writes all of
// out itself when gamma != 0; the two kernels run on parallel graph branches,
// so exactly one touches out). Data loads issue before the gamma check so the
// gamma latency overlaps them. Evict-first both directions (zero reuse).
// ---------------------------------------------------------------------------
__global__ void __launch_bounds__(CPY_NT, 4)
copy_kernel(const float4* __restrict__ x, const float* __restrict__ gamma,
            float4* __restrict__ o, size_t n4) {
    const size_t stride = (size_t)gridDim.x * CPY_NT;
    size_t i = (size_t)blockIdx.x * CPY_NT + threadIdx.x;

    if (i + 3 * stride < n4) {
        // Issue all data loads first (reads of x are harmless for any gamma),
        // then the gamma load; stall resolves them together.
        float4 v0 = __ldcs(x + i);
        float4 v1 = __ldcs(x + i +     stride);
        float4 v2 = __ldcs(x + i + 2 * stride);
        float4 v3 = __ldcs(x + i + 3 * stride);
        if (__ldg(gamma) != 0.0f) return;
        __stcs(o + i,              v0);
        __stcs(o + i +     stride, v1);
        __stcs(o + i + 2 * stride, v2);
        __stcs(o + i + 3 * stride, v3);
    } else {
        if (__ldg(gamma) != 0.0f) return;
        for (; i < n4; i += stride) __stcs(o + i, __ldcs(x + i));
    }
}

// ---------------------------------------------------------------------------
// Full path (gamma != 0): gram -> softmax -> feat with grid barriers.
// Dead (early-exit) on this bench's data; runs on a parallel graph branch so
// its launch cost hides under the copy.
// ---------------------------------------------------------------------------
__global__ void __launch_bounds__(NT, 4)
full_kernel(const float* __restrict__ x,
            const float* __restrict__ gamma,
            float* __restrict__ out) {
    const float g = __ldg(gamma);
    if (g == 0.0f) return;
    const int tid = threadIdx.x;

    __shared__ float sh[2 * 32 * 33];      // 8448 B, reused across phases

    // ---- Phase 1: Gram matrix g_att[b,c,d] = sum_n y[b,c,n] y[b,d,n] ----
    {
        float (*As)[33] = (float(*)[33])sh;
        float (*Bs)[33] = (float(*)[33])(sh + 32 * 33);
        const int tx = tid & 15, ty = tid >> 4;           // 16 x 16
        const int TILES_X = CH / 32;                      // 16
        const int TILES   = BATCH * TILES_X * TILES_X;    // 2048

        for (int tile = blockIdx.x; tile < TILES; tile += NB) {
            int b  = tile / (TILES_X * TILES_X);
            int r2 = tile % (TILES_X * TILES_X);
            int ci = (r2 / TILES_X) * 32;
            int cj = (r2 % TILES_X) * 32;
            const float* yb = x + (size_t)b * CH * HW;

            float acc00 = 0.f, acc01 = 0.f, acc10 = 0.f, acc11 = 0.f;
            for (int k0 = 0; k0 < HW; k0 += 32) {
                #pragma unroll
                for (int i = 0; i < 4; i++) {
                    int idx = tid + i * 256;
                    int r = idx >> 5, c = idx & 31;
                    As[r][c] = yb[(size_t)(ci + r) * HW + k0 + c];
                    Bs[r][c] = yb[(size_t)(cj + r) * HW + k0 + c];
                }
                __syncthreads();
                #pragma unroll
                for (int k = 0; k < 32; k++) {
                    float a0 = As[ty * 2][k],     a1 = As[ty * 2 + 1][k];
                    float b0 = Bs[tx * 2][k],     b1 = Bs[tx * 2 + 1][k];
                    acc00 += a0 * b0;  acc01 += a0 * b1;
                    acc10 += a1 * b0;  acc11 += a1 * b1;
                }
                __syncthreads();
            }
            float* gp = g_att + (size_t)b * CH * CH;
            gp[(size_t)(ci + ty * 2    ) * CH + cj + tx * 2    ] = acc00;
            gp[(size_t)(ci + ty * 2    ) * CH + cj + tx * 2 + 1] = acc01;
            gp[(size_t)(ci + ty * 2 + 1) * CH + cj + tx * 2    ] = acc10;
            gp[(size_t)(ci + ty * 2 + 1) * CH + cj + tx * 2 + 1] = acc11;
            __syncthreads();
        }
    }
    grid_barrier();

    // ---- Phase 2: softmax(rowmax - s) = exp(min-s)/sum exp(min-s) ----
    {
        float* red = sh;
        for (int row = blockIdx.x; row < BATCH * CH; row += NB) {
            float* p = g_att + (size_t)row * CH;
            float v0 = p[tid], v1 = p[tid + 256];
            red[tid] = fminf(v0, v1);
            __syncthreads();
            for (int s = 128; s > 0; s >>= 1) {
                if (tid < s) red[tid] = fminf(red[tid], red[tid + s]);
                __syncthreads();
            }
            float mn = red[0];
            __syncthreads();
            float e0 = expf(mn - v0), e1 = expf(mn - v1);
            red[tid] = e0 + e1;
            __syncthreads();
            for (int s = 128; s > 0; s >>= 1) {
                if (tid < s) red[tid] += red[tid + s];
                __syncthreads();
            }
            float inv = 1.0f / red[0];
            __syncthreads();
            p[tid]       = e0 * inv;
            p[tid + 256] = e1 * inv;
        }
    }
    grid_barrier();

    // ---- Phase 3: out[b,c,n] = g * sum_d att[b,c,d] y[b,d,n] + x[b,c,n] ----
    {
        float* a = sh;
        for (int row = blockIdx.x; row < BATCH * CH; row += NB) {
            int b = row / CH;
            const float* att = g_att + (size_t)row * CH;
            __syncthreads();
            a[tid]       = att[tid];
            a[tid + 256] = att[tid + 256];
            __syncthreads();
            const float* yb = x + (size_t)b * CH * HW;
            size_t rb = (size_t)row * HW;
            for (int n = tid; n < HW; n += NT) {
                float acc = 0.f;
                #pragma unroll 8
                for (int d = 0; d < CH; d++)
                    acc += a[d] * yb[(size_t)d * HW + n];
                out[rb + n] = g * acc + x[rb + n];
            }
        }
    }
}

// ---------------------------------------------------------------------------
extern "C" void kernel_launch(void* const* d_in, const int* in_sizes, int n_in,
                              void* d_out, int out_size) {
    const float* x     = (const float*)d_in[0];
    const float* gamma = (const float*)d_in[1];
    float*       out   = (float*)d_out;

    // One-time host-side resources (created on the uncaptured correctness
    // call; no device memory involved).
    static cudaStream_t s1 = nullptr;
    static cudaEvent_t  evA = nullptr, evB = nullptr;
    if (s1 == nullptr) {
        cudaStreamCreateWithFlags(&s1, cudaStreamNonBlocking);
        cudaEventCreateWithFlags(&evA, cudaEventDisableTiming);
        cudaEventCreateWithFlags(&evB, cudaEventDisableTiming);
    }

    // Fork: full_kernel (gamma != 0 path, dead here) on a parallel branch.
    cudaEventRecord(evA, 0);
    cudaStreamWaitEvent(s1, evA, 0);
    full_kernel<<<NB, NT, 0, s1>>>(x, gamma, out);
    cudaEventRecord(evB, s1);

    // Main branch: conditional streaming copy (gamma == 0 path).
    size_t n4 = (size_t)out_size >> 2;                       // 9,437,184
    int blocks = (int)((n4 + CPY_NT * CPY_UNR - 1) / (CPY_NT * CPY_UNR)); // 4608
    copy_kernel<<<blocks, CPY_NT>>>((const float4*)x, gamma, (float4*)out, n4);

    // Join.
    cudaStreamWaitEvent(0, evB, 0);
}

// round 9
// speedup vs baseline: 1.0075x; 1.0075x over previous
#include <cuda_runtime.h>

#define BATCH 8
#define CH    512
#define HW    9216        // 96*96
#define NB    148         // one block per SM (all-resident for grid barrier)
#define NT    256         // full-path block size

#define CPY_NT   512      // copy block size
#define CPY_UNR  4        // float4 per thread

// Scratch for the gamma != 0 path (never exercised by this bench's data,
// but kept correct for arbitrary gamma).
__device__ float g_att[(size_t)BATCH * CH * CH];   // 8 MB

// Generation-based software grid barrier (gamma != 0 path only).
__device__ unsigned g_count = 0;
__device__ volatile unsigned g_gen = 0;

__device__ __forceinline__ void grid_barrier() {
    __syncthreads();
    __threadfence();
    if (threadIdx.x == 0) {
        unsigned gen = g_gen;
        if (atomicAdd(&g_count, 1) == NB - 1) {
            g_count = 0;
            __threadfence();
            g_gen = gen + 1;
        } else {
            while (g_gen == gen) { __nanosleep(64); }
        }
    }
    __syncthreads();
}

// ---------------------------------------------------------------------------
// Streaming copy: out = x, UNCONDITIONAL. Correct for any gamma because the
// serialized full_kernel afterwards overwrites every element of out when
// gamma != 0. No gamma load -> no first-wave gamma stall. Evict-first hints
// both directions (zero-reuse stream).
// ---------------------------------------------------------------------------
__global__ void __launch_bounds__(CPY_NT, 4)
copy_kernel(const float4* __restrict__ x, float4* __restrict__ o, size_t n4) {
    const size_t stride = (size_t)gridDim.x * CPY_NT;
    size_t i = (size_t)blockIdx.x * CPY_NT + threadIdx.x;

    if (i + 3 * stride < n4) {
        float4 v0 = __ldcs(x + i);
        float4 v1 = __ldcs(x + i +     stride);
        float4 v2 = __ldcs(x + i + 2 * stride);
        float4 v3 = __ldcs(x + i + 3 * stride);
        __stcs(o + i,              v0);
        __stcs(o + i +     stride, v1);
        __stcs(o + i + 2 * stride, v2);
        __stcs(o + i + 3 * stride, v3);
    } else {
        for (; i < n4; i += stride) __stcs(o + i, __ldcs(x + i));
    }
}

// ---------------------------------------------------------------------------
// Full path (gamma != 0): gram -> softmax -> feat with grid barriers.
// Dead (early-exit, ~1.5us) on this bench's data.
// ---------------------------------------------------------------------------
__global__ void __launch_bounds__(NT, 4)
full_kernel(const float* __restrict__ x,
            const float* __restrict__ gamma,
            float* __restrict__ out) {
    const float g = __ldg(gamma);
    if (g == 0.0f) return;
    const int tid = threadIdx.x;

    __shared__ float sh[2 * 32 * 33];      // 8448 B, reused across phases

    // ---- Phase 1: Gram matrix g_att[b,c,d] = sum_n y[b,c,n] y[b,d,n] ----
    {
        float (*As)[33] = (float(*)[33])sh;
        float (*Bs)[33] = (float(*)[33])(sh + 32 * 33);
        const int tx = tid & 15, ty = tid >> 4;           // 16 x 16
        const int TILES_X = CH / 32;                      // 16
        const int TILES   = BATCH * TILES_X * TILES_X;    // 2048

        for (int tile = blockIdx.x; tile < TILES; tile += NB) {
            int b  = tile / (TILES_X * TILES_X);
            int r2 = tile % (TILES_X * TILES_X);
            int ci = (r2 / TILES_X) * 32;
            int cj = (r2 % TILES_X) * 32;
            const float* yb = x + (size_t)b * CH * HW;

            float acc00 = 0.f, acc01 = 0.f, acc10 = 0.f, acc11 = 0.f;
            for (int k0 = 0; k0 < HW; k0 += 32) {
                #pragma unroll
                for (int i = 0; i < 4; i++) {
                    int idx = tid + i * 256;
                    int r = idx >> 5, c = idx & 31;
                    As[r][c] = yb[(size_t)(ci + r) * HW + k0 + c];
                    Bs[r][c] = yb[(size_t)(cj + r) * HW + k0 + c];
                }
                __syncthreads();
                #pragma unroll
                for (int k = 0; k < 32; k++) {
                    float a0 = As[ty * 2][k],     a1 = As[ty * 2 + 1][k];
                    float b0 = Bs[tx * 2][k],     b1 = Bs[tx * 2 + 1][k];
                    acc00 += a0 * b0;  acc01 += a0 * b1;
                    acc10 += a1 * b0;  acc11 += a1 * b1;
                }
                __syncthreads();
            }
            float* gp = g_att + (size_t)b * CH * CH;
            gp[(size_t)(ci + ty * 2    ) * CH + cj + tx * 2    ] = acc00;
            gp[(size_t)(ci + ty * 2    ) * CH + cj + tx * 2 + 1] = acc01;
            gp[(size_t)(ci + ty * 2 + 1) * CH + cj + tx * 2    ] = acc10;
            gp[(size_t)(ci + ty * 2 + 1) * CH + cj + tx * 2 + 1] = acc11;
            __syncthreads();
        }
    }
    grid_barrier();

    // ---- Phase 2: softmax(rowmax - s) = exp(min-s)/sum exp(min-s) ----
    {
        float* red = sh;
        for (int row = blockIdx.x; row < BATCH * CH; row += NB) {
            float* p = g_att + (size_t)row * CH;
            float v0 = p[tid], v1 = p[tid + 256];
            red[tid] = fminf(v0, v1);
            __syncthreads();
            for (int s = 128; s > 0; s >>= 1) {
                if (tid < s) red[tid] = fminf(red[tid], red[tid + s]);
                __syncthreads();
            }
            float mn = red[0];
            __syncthreads();
            float e0 = expf(mn - v0), e1 = expf(mn - v1);
            red[tid] = e0 + e1;
            __syncthreads();
            for (int s = 128; s > 0; s >>= 1) {
                if (tid < s) red[tid] += red[tid + s];
                __syncthreads();
            }
            float inv = 1.0f / red[0];
            __syncthreads();
            p[tid]       = e0 * inv;
            p[tid + 256] = e1 * inv;
        }
    }
    grid_barrier();

    // ---- Phase 3: out[b,c,n] = g * sum_d att[b,c,d] y[b,d,n] + x[b,c,n] ----
    {
        float* a = sh;
        for (int row = blockIdx.x; row < BATCH * CH; row += NB) {
            int b = row / CH;
            const float* att = g_att + (size_t)row * CH;
            __syncthreads();
            a[tid]       = att[tid];
            a[tid + 256] = att[tid + 256];
            __syncthreads();
            const float* yb = x + (size_t)b * CH * HW;
            size_t rb = (size_t)row * HW;
            for (int n = tid; n < HW; n += NT) {
                float acc = 0.f;
                #pragma unroll 8
                for (int d = 0; d < CH; d++)
                    acc += a[d] * yb[(size_t)d * HW + n];
                out[rb + n] = g * acc + x[rb + n];
            }
        }
    }
}

// ---------------------------------------------------------------------------
extern "C" void kernel_launch(void* const* d_in, const int* in_sizes, int n_in,
                              void* d_out, int out_size) {
    const float* x     = (const float*)d_in[0];
    const float* gamma = (const float*)d_in[1];
    float*       out   = (float*)d_out;

    // Plain serial graph: 2 kernel nodes, no event nodes (events cost ~3-4us
    // per replay, more than the dead kernel they were hiding).
    size_t n4 = (size_t)out_size >> 2;                       // 9,437,184
    int blocks = (int)(n4 / (CPY_NT * CPY_UNR));             // 4608, exact
    copy_kernel<<<blocks, CPY_NT>>>((const float4*)x, (float4*)out, n4);

    // gamma != 0 path (dead launch on this bench's data); overwrites out
    // entirely when live, so the unconditional copy above stays correct.
    full_kernel<<<NB, NT>>>(x, gamma, out);
}

// round 10
// speedup vs baseline: 1.0773x; 1.0693x over previous
#include <cuda_runtime.h>

#define BATCH 8
#define CH    512
#define HW    9216        // 96*96
#define NB    148         // blocks participating in the gamma!=0 path
#define NT    512         // threads per block (both paths)
#define UNR   4           // float4 per thread in copy path

// Scratch for the gamma != 0 path (never exercised by this bench's data,
// but kept correct for arbitrary gamma).
__device__ float g_att[(size_t)BATCH * CH * CH];   // 8 MB

// Generation-based software grid barrier (gamma != 0 path only; only the
// NB low-index blocks participate, and those are trivially all resident).
__device__ unsigned g_count = 0;
__device__ volatile unsigned g_gen = 0;

__device__ __forceinline__ void grid_barrier() {
    __syncthreads();
    __threadfence();
    if (threadIdx.x == 0) {
        unsigned gen = g_gen;
        if (atomicAdd(&g_count, 1) == NB - 1) {
            g_count = 0;
            __threadfence();
            g_gen = gen + 1;
        } else {
            while (g_gen == gen) { __nanosleep(64); }
        }
    }
    __syncthreads();
}

// ---------------------------------------------------------------------------
// Single fused kernel.
//   gamma == 0 : all blocks stream out = x (float4, evict-first, 4/thread).
//   gamma != 0 : blocks >= NB exit; blocks < NB run gram -> softmax -> feat
//                phased by the software grid barrier.
// ---------------------------------------------------------------------------
__global__ void __launch_bounds__(NT, 2)
fused_kernel(const float4* __restrict__ x4, const float* __restrict__ gamma,
             float4* __restrict__ o4, size_t n4) {
    const int tid = threadIdx.x;
    const size_t stride = (size_t)gridDim.x * NT;
    size_t i = (size_t)blockIdx.x * NT + tid;

    // Speculatively issue copy loads (reads of x are safe for any gamma),
    // then the gamma load resolves while they are in flight.
    const bool main_path = (i + 3 * stride < n4);
    float4 v0, v1, v2, v3;
    if (main_path) {
        v0 = __ldcs(x4 + i);
        v1 = __ldcs(x4 + i +     stride);
        v2 = __ldcs(x4 + i + 2 * stride);
        v3 = __ldcs(x4 + i + 3 * stride);
    }
    const float g = __ldg(gamma);

    if (g == 0.0f) {                       // ---- FAST PATH: out = x ----
        if (main_path) {
            __stcs(o4 + i,              v0);
            __stcs(o4 + i +     stride, v1);
            __stcs(o4 + i + 2 * stride, v2);
            __stcs(o4 + i + 3 * stride, v3);
        } else {
            for (; i < n4; i += stride) __stcs(o4 + i, __ldcs(x4 + i));
        }
        return;
    }

    // ---- FULL PATH (gamma != 0) ----
    if (blockIdx.x >= NB) return;
    const float* __restrict__ x   = (const float*)x4;
    float*       __restrict__ out = (float*)o4;

    __shared__ float sh[2 * 32 * 33];      // 8448 B, reused across phases

    // ---- Phase 1: Gram matrix g_att[b,c,d] = sum_n y[b,c,n] y[b,d,n] ----
    {
        float (*As)[33] = (float(*)[33])sh;
        float (*Bs)[33] = (float(*)[33])(sh + 32 * 33);
        const int tx = tid & 15, ty = (tid >> 4) & 15;    // 16x16 (tid<256)
        const int TILES_X = CH / 32;                      // 16
        const int TILES   = BATCH * TILES_X * TILES_X;    // 2048

        for (int tile = blockIdx.x; tile < TILES; tile += NB) {
            int b  = tile / (TILES_X * TILES_X);
            int r2 = tile % (TILES_X * TILES_X);
            int ci = (r2 / TILES_X) * 32;
            int cj = (r2 % TILES_X) * 32;
            const float* yb = x + (size_t)b * CH * HW;

            float acc00 = 0.f, acc01 = 0.f, acc10 = 0.f, acc11 = 0.f;
            for (int k0 = 0; k0 < HW; k0 += 32) {
                #pragma unroll
                for (int ii = 0; ii < 2; ii++) {          // 512 thr x 2 = 1024
                    int idx = tid + ii * NT;
                    int r = idx >> 5, c = idx & 31;
                    As[r][c] = yb[(size_t)(ci + r) * HW + k0 + c];
                    Bs[r][c] = yb[(size_t)(cj + r) * HW + k0 + c];
                }
                __syncthreads();
                if (tid < 256) {
                    #pragma unroll
                    for (int k = 0; k < 32; k++) {
                        float a0 = As[ty * 2][k],     a1 = As[ty * 2 + 1][k];
                        float b0 = Bs[tx * 2][k],     b1 = Bs[tx * 2 + 1][k];
                        acc00 += a0 * b0;  acc01 += a0 * b1;
                        acc10 += a1 * b0;  acc11 += a1 * b1;
                    }
                }
                __syncthreads();
            }
            if (tid < 256) {
                float* gp = g_att + (size_t)b * CH * CH;
                gp[(size_t)(ci + ty * 2    ) * CH + cj + tx * 2    ] = acc00;
                gp[(size_t)(ci + ty * 2    ) * CH + cj + tx * 2 + 1] = acc01;
                gp[(size_t)(ci + ty * 2 + 1) * CH + cj + tx * 2    ] = acc10;
                gp[(size_t)(ci + ty * 2 + 1) * CH + cj + tx * 2 + 1] = acc11;
            }
            __syncthreads();
        }
    }
    grid_barrier();

    // ---- Phase 2: softmax(rowmax - s) = exp(min-s)/sum exp(min-s) ----
    {
        float* red = sh;                                  // 512 floats
        for (int row = blockIdx.x; row < BATCH * CH; row += NB) {
            float* p = g_att + (size_t)row * CH;
            float v = p[tid];                             // CH == NT == 512
            red[tid] = v;
            __syncthreads();
            for (int s = 256; s > 0; s >>= 1) {
                if (tid < s) red[tid] = fminf(red[tid], red[tid + s]);
                __syncthreads();
            }
            float mn = red[0];
            __syncthreads();
            float e = expf(mn - v);
            red[tid] = e;
            __syncthreads();
            for (int s = 256; s > 0; s >>= 1) {
                if (tid < s) red[tid] += red[tid + s];
                __syncthreads();
            }
            float inv = 1.0f / red[0];
            p[tid] = e * inv;
            __syncthreads();
        }
    }
    grid_barrier();

    // ---- Phase 3: out[b,c,n] = g * sum_d att[b,c,d] y[b,d,n] + x[b,c,n] ----
    {
        float* a = sh;                                    // 512 floats
        for (int row = blockIdx.x; row < BATCH * CH; row += NB) {
            int b = row / CH;
            const float* att = g_att + (size_t)row * CH;
            __syncthreads();
            a[tid] = att[tid];
            __syncthreads();
            const float* yb = x + (size_t)b * CH * HW;
            size_t rb = (size_t)row * HW;
            for (int n = tid; n < HW; n += NT) {
                float acc = 0.f;
                #pragma unroll 8
                for (int d = 0; d < CH; d++)
                    acc += a[d] * yb[(size_t)d * HW + n];
                out[rb + n] = g * acc + x[rb + n];
            }
        }
    }
}

// ---------------------------------------------------------------------------
extern "C" void kernel_launch(void* const* d_in, const int* in_sizes, int n_in,
                              void* d_out, int out_size) {
    const float* x     = (const float*)d_in[0];
    const float* gamma = (const float*)d_in[1];
    float*       out   = (float*)d_out;

    // Single kernel node: second-launch overhead (~4us) eliminated.
    size_t n4 = (size_t)out_size >> 2;                   // 9,437,184
    int blocks = (int)(n4 / ((size_t)NT * UNR));         // 4608, exact
    fused_kernel<<<blocks, NT>>>((const float4*)x, gamma, (float4*)out, n4);
}